// round 1
// baseline (speedup 1.0000x reference)
#include <cuda_runtime.h>
#include <cuda_bf16.h>

// HungarianMatcher cost matrix:
//   out[b,q,t] = L1(span) + (-GIoU) + cost_class + cost_reference
// Flattened: 19200 rows (bs*nq) x 1280 targets, fp32 output (98.3 MB -> write-bound).
//
// Fusion: -giou = -iou + 1 - union/enclose, and in (cx,w) space area == w, so
//   cost = |pcx-tcx| + |pw-tw| + C_row - inter/union - union/enclose
// with C_row = cost_class + cost_ref + 1 precomputed per row.

#define QPER 8
#define NTHREADS 320   // 320 threads * 4 targets = 1280 = T
#define TMAX 1280

__device__ __forceinline__ float cost_el(
    float cx, float w, float x1, float x2, float crow,
    float tc, float twv, float t1, float t2)
{
    float l1    = fabsf(cx - tc) + fabsf(w - twv);
    float lt    = fmaxf(x1, t1);
    float rb    = fminf(x2, t2);
    float inter = fmaxf(rb - lt, 0.0f);
    float uni   = w + twv - inter;
    float left  = fminf(x1, t1);
    float right = fmaxf(x2, t2);
    float enc   = right - left;
    return l1 + crow - __fdividef(inter, uni) - __fdividef(uni, enc);
}

__global__ __launch_bounds__(NTHREADS)
void hm_cost_kernel(const float* __restrict__ logits,
                    const float* __restrict__ spans,
                    const float* __restrict__ tgt,
                    const float* __restrict__ ref,
                    float* __restrict__ out,
                    int T)
{
    __shared__ float s_tcx[TMAX], s_tw[TMAX], s_tx1[TMAX], s_tx2[TMAX];
    __shared__ float s_qcx[QPER], s_qw[QPER], s_qx1[QPER], s_qx2[QPER], s_qc[QPER];

    const int tid  = threadIdx.x;
    const int row0 = blockIdx.x * QPER;

    // Load targets into SoA shared (cx, w, x1, x2). Coalesced float2 global loads.
    const float2* t2 = reinterpret_cast<const float2*>(tgt);
    for (int j = tid; j < T; j += NTHREADS) {
        float2 s = t2[j];
        s_tcx[j] = s.x;
        s_tw[j]  = s.y;
        s_tx1[j] = s.x - 0.5f * s.y;
        s_tx2[j] = s.x + 0.5f * s.y;
    }

    // Per-row constants, computed cooperatively (one thread per row).
    if (tid < QPER) {
        int r = row0 + tid;
        float2 s  = reinterpret_cast<const float2*>(spans)[r];
        float cx = s.x, w = s.y;
        float x1 = cx - 0.5f * w;
        float x2 = cx + 0.5f * w;
        float2 lg = reinterpret_cast<const float2*>(logits)[r];
        // softmax over 2 classes, prob of class 0 -> sigmoid(l0 - l1)
        float cc = -1.0f / (1.0f + __expf(lg.y - lg.x));
        float2 rp = reinterpret_cast<const float2*>(ref)[r];
        float d0 = x1 - rp.x;
        float d1 = x2 - rp.y;
        float cr = sqrtf(d0 * d0 + d1 * d1);
        s_qcx[tid] = cx;
        s_qw[tid]  = w;
        s_qx1[tid] = x1;
        s_qx2[tid] = x2;
        s_qc[tid]  = cc + cr + 1.0f;   // +1 folded from the GIoU rearrangement
    }
    __syncthreads();

    // Each thread owns 4 consecutive targets; hoist them into registers,
    // reused across all QPER rows.
    const int tb = tid * 4;
    float4 tc = *reinterpret_cast<const float4*>(&s_tcx[tb]);
    float4 tw = *reinterpret_cast<const float4*>(&s_tw[tb]);
    float4 t1 = *reinterpret_cast<const float4*>(&s_tx1[tb]);
    float4 t2v = *reinterpret_cast<const float4*>(&s_tx2[tb]);

    #pragma unroll
    for (int q = 0; q < QPER; q++) {
        float cx = s_qcx[q], w = s_qw[q], x1 = s_qx1[q], x2 = s_qx2[q], c = s_qc[q];
        float4 o;
        o.x = cost_el(cx, w, x1, x2, c, tc.x, tw.x, t1.x, t2v.x);
        o.y = cost_el(cx, w, x1, x2, c, tc.y, tw.y, t1.y, t2v.y);
        o.z = cost_el(cx, w, x1, x2, c, tc.z, tw.z, t1.z, t2v.z);
        o.w = cost_el(cx, w, x1, x2, c, tc.w, tw.w, t1.w, t2v.w);
        float4* orow = reinterpret_cast<float4*>(out + (size_t)(row0 + q) * T);
        orow[tid] = o;
    }
}

extern "C" void kernel_launch(void* const* d_in, const int* in_sizes, int n_in,
                              void* d_out, int out_size)
{
    const float* logits = (const float*)d_in[0];  // [bs, nq, 2]
    const float* spans  = (const float*)d_in[1];  // [bs, nq, 2]
    const float* tgt    = (const float*)d_in[2];  // [T, 2]
    const float* ref    = (const float*)d_in[3];  // [bs, nq, 2]
    float* out = (float*)d_out;

    int nrows = in_sizes[1] / 2;   // bs*nq = 19200
    int T     = in_sizes[2] / 2;   // 1280

    int blocks = nrows / QPER;     // 2400
    hm_cost_kernel<<<blocks, NTHREADS>>>(logits, spans, tgt, ref, out, T);
}